// round 12
// baseline (speedup 1.0000x reference)
#include <cuda_runtime.h>
#include <cuda_bf16.h>
#include <cstdint>

#define L2E 1.4426950408889634f
#define BATCH 64
#define SEQ 512
#define HID 768
#define NC 21
#define EM_STRIDE (SEQ * NC)

#define BM 64
#define ASTRIDE 144           // bytes per A row in smem (64 bf16 + 8 pad)
#define NFRAG (12 * 4 * 3)    // k16-chunks x n8-tiles

__device__ __align__(16) float g_emx[BATCH * SEQ * NC];   // linear emissions 2^em2
__device__ __align__(16) uint32_t g_wfrag[NFRAG * 64];    // W bf16, mma-frag order
__device__ __align__(16) float g_cmat[BATCH][8][NC * 24]; // chunk transfer matrices
__device__ float g_coffe[BATCH][8];                       // chunk exponent offsets
__device__ float g_res[BATCH];
__device__ int g_bcnt[BATCH];   // per-batch chunk-done counters (self-reset)
__device__ int g_done;          // combines-finished counter (self-reset)

__device__ __forceinline__ float fast_ex2(float x) {
    float y; asm("ex2.approx.ftz.f32 %0, %1;" : "=f"(y) : "f"(x)); return y;
}
__device__ __forceinline__ float fast_lg2(float x) {
    float y; asm("lg2.approx.ftz.f32 %0, %1;" : "=f"(y) : "f"(x)); return y;
}
__device__ __forceinline__ uint32_t smem_u32(const void* p) {
    uint32_t a;
    asm("{ .reg .u64 t; cvta.to.shared.u64 t, %1; cvt.u32.u64 %0, t; }" : "=r"(a) : "l"(p));
    return a;
}

// ---------------------------------------------------------------------------
// Kernel 0: pack W into mma B-fragment order (see R10).
// ---------------------------------------------------------------------------
__global__ void pack_w_kernel(const float* __restrict__ W) {
    int o = blockIdx.x * blockDim.x + threadIdx.x;
    if (o >= NFRAG * 64) return;
    int h    = o & 1;
    int lane = (o >> 1) & 31;
    int f    = o >> 6;
    int nt   = f % 3;
    int kc   = f / 3;
    int k    = (kc >> 2) * 64 + (kc & 3) * 16 + (lane & 3) * 2 + h * 8;
    int n    = nt * 8 + (lane >> 2);
    float w0 = (n < NC) ? W[k * NC + n]       : 0.f;
    float w1 = (n < NC) ? W[(k + 1) * NC + n] : 0.f;
    uint32_t pk;
    asm("cvt.rn.satfinite.bf16x2.f32 %0, %1, %2;" : "=r"(pk) : "f"(w1), "f"(w0));
    g_wfrag[o] = pk;
}

// ---------------------------------------------------------------------------
// Fused kernel, CTA (b,c) = blockIdx (8 per batch):
//  1) gemm 64 emission rows (mma.sync bf16), keep emx in smem + store global
//  2) compute this chunk's 21x21 transfer matrix M_c by serial matmul chain
//     over its own 64 timesteps (pow-2 renorm per step) -> g_cmat
//  3) 8th arriver per batch: numerator + 8 matvecs through chunk matrices
//     + logZ;  64th finisher: final loss reduction.
// ---------------------------------------------------------------------------
__global__ __launch_bounds__(128) void fused_kernel(
    const float* __restrict__ hidden,
    const float* __restrict__ bias,
    const float* __restrict__ start_t,
    const float* __restrict__ end_t,
    const float* __restrict__ trans,
    const int*   __restrict__ labr,
    float* __restrict__ out)
{
    __shared__ __align__(1024) uint8_t a_sm[2][BM * ASTRIDE];   // 18432 B (gemm)
    __shared__ __align__(16) float smf[BM * NC];                // own emx rows
    __shared__ __align__(16) float Tlin[NC * 24];               // 2^(trans*L2E)
    __shared__ __align__(16) float Mb[2][NC * 24];              // matmul ping-pong
    __shared__ __align__(16) float av[2][24];
    __shared__ float red_f[128];
    __shared__ int   red_i[128];
    __shared__ float s_num2;
    __shared__ int   s_len, s_flag, s_last;

    const int tid   = threadIdx.x;
    const int wid   = tid >> 5;
    const int lane  = tid & 31;
    const int row0  = blockIdx.x * BM;
    const int batch = blockIdx.x >> 3;
    const int chunk = blockIdx.x & 7;

    // ================= GEMM phase =================
    float acc[3][4];
#pragma unroll
    for (int i = 0; i < 3; i++)
#pragma unroll
        for (int j = 0; j < 4; j++) acc[i][j] = 0.f;

    auto fill = [&](int ch, int st) {
        const int k0 = ch * 64;
#pragma unroll
        for (int u = 0; u < 16; u++) {
            int p = tid + u * 128;
            int r = p >> 5, kp = p & 31;
            float2 hv = *reinterpret_cast<const float2*>(
                hidden + (uint64_t)(row0 + r) * HID + k0 + 2 * kp);
            uint32_t bfx;
            asm("cvt.rn.satfinite.bf16x2.f32 %0, %1, %2;" : "=r"(bfx) : "f"(hv.y), "f"(hv.x));
            *reinterpret_cast<uint32_t*>(a_sm[st] + r * ASTRIDE + kp * 4) = bfx;
        }
    };

    fill(0, 0);
    __syncthreads();

    const int rowA = wid * 16 + (lane & 7) + ((lane >> 3) & 1) * 8;
    const int aoff = rowA * ASTRIDE + ((lane >> 4) * 16);

    for (int ch = 0; ch < 12; ch++) {
        if (ch + 1 < 12) fill(ch + 1, (ch + 1) & 1);
        const uint32_t abase = smem_u32(a_sm[ch & 1] + aoff);
#pragma unroll
        for (int ksub = 0; ksub < 4; ksub++) {
            uint32_t a0, a1, a2, a3;
            asm volatile("ldmatrix.sync.aligned.m8n8.x4.shared.b16 {%0,%1,%2,%3}, [%4];"
                : "=r"(a0), "=r"(a1), "=r"(a2), "=r"(a3)
                : "r"(abase + ksub * 32));
            const int fbase = ((ch * 4 + ksub) * 3) * 64 + lane * 2;
#pragma unroll
            for (int nt = 0; nt < 3; nt++) {
                uint2 b = *reinterpret_cast<const uint2*>(&g_wfrag[fbase + nt * 64]);
                asm volatile("mma.sync.aligned.m16n8k16.row.col.f32.bf16.bf16.f32 "
                    "{%0,%1,%2,%3}, {%4,%5,%6,%7}, {%8,%9}, {%0,%1,%2,%3};"
                    : "+f"(acc[nt][0]), "+f"(acc[nt][1]), "+f"(acc[nt][2]), "+f"(acc[nt][3])
                    : "r"(a0), "r"(a1), "r"(a2), "r"(a3), "r"(b.x), "r"(b.y));
            }
        }
        __syncthreads();
    }

    // epilogue: frag -> emx -> smf -> coalesced store to g_emx
    {
        const int r0 = wid * 16 + (lane >> 2);
#pragma unroll
        for (int nt = 0; nt < 3; nt++) {
            int c = nt * 8 + (lane & 3) * 2;
            if (c < NC) {
                float bc = bias[c];
                smf[r0 * NC + c]       = fast_ex2((acc[nt][0] + bc) * L2E);
                smf[(r0 + 8) * NC + c] = fast_ex2((acc[nt][2] + bc) * L2E);
            }
            if (c + 1 < NC) {
                float bc = bias[c + 1];
                smf[r0 * NC + c + 1]       = fast_ex2((acc[nt][1] + bc) * L2E);
                smf[(r0 + 8) * NC + c + 1] = fast_ex2((acc[nt][3] + bc) * L2E);
            }
        }
        __syncthreads();
        float4* dst = reinterpret_cast<float4*>(g_emx + (uint64_t)row0 * NC);
        const float4* src = reinterpret_cast<const float4*>(smf);
        for (int i = tid; i < (BM * NC) / 4; i += 128) dst[i] = src[i];
    }

    // ================= labels: dtype + len =================
    int ok = 1;
    for (int t = tid; t < SEQ; t += 128) {
        int v = labr[2 * t + 1];
        if (v != 0 && v != -1) ok = 0;
    }
    int is64 = __syncthreads_and(ok);
    const int lbase = is64 ? batch * SEQ * 2 : batch * SEQ;
    const int lstep = is64 ? 2 : 1;
#define LAB(t) labr[lbase + (t) * lstep]
    {
        int cnt = 0;
        for (int t = tid; t < SEQ; t += 128)
            if (LAB(t) != -100) cnt++;
        red_i[tid] = cnt;
        __syncthreads();
        for (int s = 64; s > 0; s >>= 1) {
            if (tid < s) red_i[tid] += red_i[tid + s];
            __syncthreads();
        }
        if (tid == 0) s_len = red_i[0];
        __syncthreads();
    }
    const int len = s_len;

    // ================= chunk transfer matrix =================
    for (int i = tid; i < NC * 24; i += 128) {
        int r = i / 24, c = i % 24;
        Tlin[i] = (c < NC) ? fast_ex2(trans[r * NC + c] * L2E) : 0.f;
    }
    __syncthreads();

    const int  i21    = tid / 6;          // 0..20 for tid<126
    const int  j0     = (tid % 6) * 4;
    const bool active = (tid < 126);
    const int  tlo    = (chunk == 0) ? 1 : chunk * 64;
    const int  thi    = min((chunk + 1) * 64, len);
    float offe = 0.f;
    int   p    = 0;

    if (thi > tlo) {
        if (active) {   // M = T · diag(em_tlo)
            int l = tlo - chunk * 64;
            float4 tv = *reinterpret_cast<const float4*>(&Tlin[i21 * 24 + j0]);
            float4 o;
            o.x = tv.x * ((j0     < NC) ? smf[l * NC + j0]     : 0.f);
            o.y = tv.y * ((j0 + 1 < NC) ? smf[l * NC + j0 + 1] : 0.f);
            o.z = tv.z * ((j0 + 2 < NC) ? smf[l * NC + j0 + 2] : 0.f);
            o.w = tv.w * ((j0 + 3 < NC) ? smf[l * NC + j0 + 3] : 0.f);
            *reinterpret_cast<float4*>(&Mb[0][i21 * 24 + j0]) = o;
        }
        __syncthreads();
        for (int t = tlo + 1; t < thi; t++) {
            if (active) {
                const float* Mp = Mb[p];
                float sx = 0.f, sy = 0.f, sz = 0.f, sw = 0.f;
#pragma unroll
                for (int k = 0; k < NC; k++) {
                    float m = Mp[i21 * 24 + k];
                    float4 tv = *reinterpret_cast<const float4*>(&Tlin[k * 24 + j0]);
                    sx += m * tv.x; sy += m * tv.y; sz += m * tv.z; sw += m * tv.w;
                }
                int   e   = ((__float_as_int(Mp[0]) >> 23) & 255) - 127;
                float scl = __int_as_float((127 - e) << 23);   // exact 2^-e
                offe += (float)e;
                int l = t - chunk * 64;
                float4 o;
                o.x = sx * scl * ((j0     < NC) ? smf[l * NC + j0]     : 0.f);
                o.y = sy * scl * ((j0 + 1 < NC) ? smf[l * NC + j0 + 1] : 0.f);
                o.z = sz * scl * ((j0 + 2 < NC) ? smf[l * NC + j0 + 2] : 0.f);
                o.w = sw * scl * ((j0 + 3 < NC) ? smf[l * NC + j0 + 3] : 0.f);
                *reinterpret_cast<float4*>(&Mb[1 - p][i21 * 24 + j0]) = o;
            }
            __syncthreads();
            p ^= 1;
        }
        if (active)
            *reinterpret_cast<float4*>(&g_cmat[batch][chunk][i21 * 24 + j0]) =
                *reinterpret_cast<const float4*>(&Mb[p][i21 * 24 + j0]);
        if (tid == 0) g_coffe[batch][chunk] = offe;
    } else {
        if (active) {   // identity chunk (fully masked)
            float4 o = {0.f, 0.f, 0.f, 0.f};
            if (i21 == j0)     o.x = 1.f;
            if (i21 == j0 + 1) o.y = 1.f;
            if (i21 == j0 + 2) o.z = 1.f;
            if (i21 == j0 + 3) o.w = 1.f;
            *reinterpret_cast<float4*>(&g_cmat[batch][chunk][i21 * 24 + j0]) = o;
        }
        if (tid == 0) g_coffe[batch][chunk] = 0.f;
    }

    // ================= handoff: 8th arriver combines =================
    __threadfence();
    if (tid == 0) s_flag = (atomicAdd(&g_bcnt[batch], 1) == 7);
    __syncthreads();
    if (!s_flag) return;
    __threadfence();

    const float* emx_g = g_emx + batch * EM_STRIDE;

    // numerator (log2 domain)
    {
        float pa = 0.f;
        for (int t = tid; t < SEQ; t += 128) {
            int l = LAB(t);
            if (l != -100) {
                if (t == 0) {
                    pa += start_t[l] * L2E + fast_lg2(emx_g[l]);
                } else {
                    int lp = LAB(t - 1);
                    pa += fast_lg2(emx_g[t * NC + l]) + trans[lp * NC + l] * L2E;
                }
            }
        }
        red_f[tid] = pa;
        __syncthreads();
        for (int s = 64; s > 0; s >>= 1) {
            if (tid < s) red_f[tid] += red_f[tid + s];
            __syncthreads();
        }
        if (tid == 0) s_num2 = red_f[0] + end_t[LAB(len - 1)] * L2E;
        __syncthreads();
    }

    // combine: a0 through 8 chunk matrices (warp 0)
    if (tid < 32) {
        const int j = lane < NC ? lane : NC - 1;
        const float endx = fast_ex2(end_t[j] * L2E);
        float a = fast_ex2(start_t[j] * L2E) * emx_g[j];
        if (lane < NC)  av[0][lane] = a;
        if (lane >= NC && lane < 24) { av[0][lane] = 0.f; av[1][lane] = 0.f; }
        float offeT = 0.f;
        int buf = 0;
#pragma unroll
        for (int c = 0; c < 8; c++) {
            __syncwarp();
            const float4* vp = reinterpret_cast<const float4*>(av[buf]);
            float4 v0 = vp[0], v1 = vp[1], v2 = vp[2],
                   v3 = vp[3], v4 = vp[4], v5 = vp[5];
            int   e   = ((__float_as_int(v0.x) >> 23) & 255) - 127;
            float scl = __int_as_float((127 - e) << 23);
            offeT += (float)e + g_coffe[batch][c];
            const float* Mc = g_cmat[batch][c];
            float s = v0.x * Mc[0 * 24 + j]  + v0.y * Mc[1 * 24 + j]
                    + v0.z * Mc[2 * 24 + j]  + v0.w * Mc[3 * 24 + j]
                    + v1.x * Mc[4 * 24 + j]  + v1.y * Mc[5 * 24 + j]
                    + v1.z * Mc[6 * 24 + j]  + v1.w * Mc[7 * 24 + j]
                    + v2.x * Mc[8 * 24 + j]  + v2.y * Mc[9 * 24 + j]
                    + v2.z * Mc[10 * 24 + j] + v2.w * Mc[11 * 24 + j]
                    + v3.x * Mc[12 * 24 + j] + v3.y * Mc[13 * 24 + j]
                    + v3.z * Mc[14 * 24 + j] + v3.w * Mc[15 * 24 + j]
                    + v4.x * Mc[16 * 24 + j] + v4.y * Mc[17 * 24 + j]
                    + v4.z * Mc[18 * 24 + j] + v4.w * Mc[19 * 24 + j]
                    + v5.x * Mc[20 * 24 + j];
            a = s * scl;
            buf ^= 1;
            if (lane < NC) av[buf][lane] = a;
        }
        __syncwarp();

        float ex = (lane < NC) ? a * endx : 0.f;
#pragma unroll
        for (int d = 16; d > 0; d >>= 1)
            ex += __shfl_xor_sync(0xffffffffu, ex, d);
        if (lane == 0)
            g_res[batch] = offeT + fast_lg2(ex) - s_num2;
    }
#undef LAB

    // ================= final loss: 64th combiner reduces =================
    __syncthreads();
    __threadfence();
    if (tid == 0) {
        g_bcnt[batch] = 0;                       // reset for graph replay
        s_last = (atomicAdd(&g_done, 1) == BATCH - 1);
    }
    __syncthreads();
    if (s_last && tid < 32) {
        float v = g_res[tid] + g_res[tid + 32];
#pragma unroll
        for (int d = 16; d > 0; d >>= 1)
            v += __shfl_xor_sync(0xffffffffu, v, d);
        if (tid == 0) {
            out[0] = v * (1.0f / (64.0f * L2E));
            g_done = 0;                          // reset for graph replay
        }
    }
}

// ---------------------------------------------------------------------------
extern "C" void kernel_launch(void* const* d_in, const int* in_sizes, int n_in,
                              void* d_out, int out_size)
{
    const float* hidden = nullptr;
    const float* W      = nullptr;
    const float* trans  = nullptr;
    const int*   labels = nullptr;
    const float* small[3] = {nullptr, nullptr, nullptr};
    int nsmall = 0;

    for (int i = 0; i < n_in; i++) {
        switch (in_sizes[i]) {
            case BATCH * SEQ * HID: hidden = (const float*)d_in[i]; break;
            case HID * NC:          W      = (const float*)d_in[i]; break;
            case NC * NC:           trans  = (const float*)d_in[i]; break;
            case BATCH * SEQ:       labels = (const int*)d_in[i];   break;
            case NC: if (nsmall < 3) small[nsmall++] = (const float*)d_in[i]; break;
            default: break;
        }
    }
    const float* bias    = small[0];
    const float* start_t = small[1];
    const float* end_t   = small[2];

    pack_w_kernel<<<(NFRAG * 64 + 255) / 256, 256>>>(W);
    fused_kernel<<<512, 128>>>(hidden, bias, start_t, end_t, trans, labels,
                               (float*)d_out);
}

// round 13
// speedup vs baseline: 1.8072x; 1.8072x over previous
#include <cuda_runtime.h>
#include <cuda_bf16.h>
#include <cstdint>

#define L2E 1.4426950408889634f
#define BATCH 64
#define SEQ 512
#define HID 768
#define NC 21
#define EM_STRIDE (SEQ * NC)

#define BM 64
#define ASTRIDE 144           // bytes per bf16 A row in smem (64 bf16 + 8 pad)
#define NFRAG (12 * 4 * 3)    // k16-chunks x n8-tiles

__device__ __align__(16) float g_emx[BATCH * SEQ * NC];   // linear emissions 2^em2
__device__ __align__(16) uint32_t g_wfrag[NFRAG * 64];    // W bf16, mma-frag order
__device__ float g_res[BATCH];
__device__ int g_bcnt[BATCH];   // per-batch gemm-CTA arrival counters (self-reset)
__device__ int g_done;          // scans-finished counter (self-reset)

__device__ __forceinline__ float fast_ex2(float x) {
    float y; asm("ex2.approx.ftz.f32 %0, %1;" : "=f"(y) : "f"(x)); return y;
}
__device__ __forceinline__ float fast_lg2(float x) {
    float y; asm("lg2.approx.ftz.f32 %0, %1;" : "=f"(y) : "f"(x)); return y;
}
__device__ __forceinline__ uint32_t smem_u32(const void* p) {
    uint32_t a;
    asm("{ .reg .u64 t; cvta.to.shared.u64 t, %1; cvt.u32.u64 %0, t; }" : "=r"(a) : "l"(p));
    return a;
}
__device__ __forceinline__ void cp_async16(void* dst, const void* src) {
    unsigned d = (unsigned)__cvta_generic_to_shared(dst);
    asm volatile("cp.async.cg.shared.global [%0], [%1], 16;" :: "r"(d), "l"(src));
}

// ---------------------------------------------------------------------------
// Kernel 0: pack W into mma B-fragment order (proven in R10).
// ---------------------------------------------------------------------------
__global__ void pack_w_kernel(const float* __restrict__ W) {
    int o = blockIdx.x * blockDim.x + threadIdx.x;
    if (o >= NFRAG * 64) return;
    int h    = o & 1;
    int lane = (o >> 1) & 31;
    int f    = o >> 6;
    int nt   = f % 3;
    int kc   = f / 3;
    int k    = (kc >> 2) * 64 + (kc & 3) * 16 + (lane & 3) * 2 + h * 8;
    int n    = nt * 8 + (lane >> 2);
    float w0 = (n < NC) ? W[k * NC + n]       : 0.f;
    float w1 = (n < NC) ? W[(k + 1) * NC + n] : 0.f;
    uint32_t pk;
    asm("cvt.rn.satfinite.bf16x2.f32 %0, %1, %2;" : "=r"(pk) : "f"(w1), "f"(w0));
    g_wfrag[o] = pk;
}

// ---------------------------------------------------------------------------
// Fused kernel (R11 structure): gemm tile -> 8th arriver scans its batch ->
// 64th scanner reduces. R13 gemm change: A staged via 2-deep cp.async fp32
// ring (no in-thread DRAM stall), then smem->smem convert to the bf16
// ldmatrix tile. mma path identical to R11.
// ---------------------------------------------------------------------------
#define USM_BYTES 44224
__global__ __launch_bounds__(128) void fused_kernel(
    const float* __restrict__ hidden,
    const float* __restrict__ bias,
    const float* __restrict__ start_t,
    const float* __restrict__ end_t,
    const float* __restrict__ trans,
    const int*   __restrict__ labr,
    float* __restrict__ out)
{
    __shared__ __align__(1024) uint8_t usm[USM_BYTES];
    __shared__ float s_num2;
    __shared__ int   s_len, s_flag, s_last;

    const int tid   = threadIdx.x;
    const int wid   = tid >> 5;
    const int lane  = tid & 31;
    const int row0  = blockIdx.x * BM;
    const int batch = blockIdx.x >> 3;

    // ================= GEMM phase =================
    // carve: fp32 ring 2 x 16KB at 0; bf16 tile 9216B at 32768  (41984 total)
    float*   f32s = reinterpret_cast<float*>(usm);
    uint8_t* tile = usm + 32768;

    float acc[3][4];
#pragma unroll
    for (int i = 0; i < 3; i++)
#pragma unroll
        for (int j = 0; j < 4; j++) acc[i][j] = 0.f;

    auto issue = [&](int ch, int st) {
        const float* src0 = hidden + (uint64_t)row0 * HID + ch * 64;
#pragma unroll
        for (int u = 0; u < 8; u++) {
            int q = tid + u * 128;            // 0..1023 (16B segs)
            int r = q >> 4, seg = q & 15;
            cp_async16(&f32s[st * 4096 + q * 4], src0 + r * HID + seg * 4);
        }
        asm volatile("cp.async.commit_group;");
    };
    auto convert = [&](int st) {
#pragma unroll
        for (int u = 0; u < 8; u++) {
            int q = tid + u * 128;
            int r = q >> 4, seg = q & 15;
            float4 v = *reinterpret_cast<const float4*>(&f32s[st * 4096 + q * 4]);
            uint32_t b0, b1;
            asm("cvt.rn.satfinite.bf16x2.f32 %0, %1, %2;" : "=r"(b0) : "f"(v.y), "f"(v.x));
            asm("cvt.rn.satfinite.bf16x2.f32 %0, %1, %2;" : "=r"(b1) : "f"(v.w), "f"(v.z));
            uint2 pk = {b0, b1};
            *reinterpret_cast<uint2*>(tile + r * ASTRIDE + seg * 8) = pk;
        }
    };

    issue(0, 0);
    issue(1, 1);

    const int rowA = wid * 16 + (lane & 7) + ((lane >> 3) & 1) * 8;
    const int aoff = rowA * ASTRIDE + ((lane >> 4) * 16);

    for (int ch = 0; ch < 12; ch++) {
        if (ch < 11) asm volatile("cp.async.wait_group 1;");
        else         asm volatile("cp.async.wait_group 0;");
        __syncthreads();                 // A: stage ch visible; prev mma done with tile
        convert(ch & 1);
        __syncthreads();                 // B: tile ready; stage ch free
        if (ch + 2 < 12) issue(ch + 2, ch & 1);

        const uint32_t abase = smem_u32(tile + aoff);
#pragma unroll
        for (int ksub = 0; ksub < 4; ksub++) {
            uint32_t a0, a1, a2, a3;
            asm volatile("ldmatrix.sync.aligned.m8n8.x4.shared.b16 {%0,%1,%2,%3}, [%4];"
                : "=r"(a0), "=r"(a1), "=r"(a2), "=r"(a3)
                : "r"(abase + ksub * 32));
            const int fbase = ((ch * 4 + ksub) * 3) * 64 + lane * 2;
#pragma unroll
            for (int nt = 0; nt < 3; nt++) {
                uint2 b = *reinterpret_cast<const uint2*>(&g_wfrag[fbase + nt * 64]);
                asm volatile("mma.sync.aligned.m16n8k16.row.col.f32.bf16.bf16.f32 "
                    "{%0,%1,%2,%3}, {%4,%5,%6,%7}, {%8,%9}, {%0,%1,%2,%3};"
                    : "+f"(acc[nt][0]), "+f"(acc[nt][1]), "+f"(acc[nt][2]), "+f"(acc[nt][3])
                    : "r"(a0), "r"(a1), "r"(a2), "r"(a3), "r"(b.x), "r"(b.y));
            }
        }
    }
    __syncthreads();   // mma done everywhere before smf aliases the fp32 ring

    // epilogue: frag -> emx -> smf (usm base) -> coalesced store
    {
        float* smf = reinterpret_cast<float*>(usm);
        const int r0 = wid * 16 + (lane >> 2);
#pragma unroll
        for (int nt = 0; nt < 3; nt++) {
            int c = nt * 8 + (lane & 3) * 2;
            if (c < NC) {
                float bc = bias[c];
                smf[r0 * NC + c]       = fast_ex2((acc[nt][0] + bc) * L2E);
                smf[(r0 + 8) * NC + c] = fast_ex2((acc[nt][2] + bc) * L2E);
            }
            if (c + 1 < NC) {
                float bc = bias[c + 1];
                smf[r0 * NC + c + 1]       = fast_ex2((acc[nt][1] + bc) * L2E);
                smf[(r0 + 8) * NC + c + 1] = fast_ex2((acc[nt][3] + bc) * L2E);
            }
        }
        __syncthreads();
        float4* dst = reinterpret_cast<float4*>(g_emx + (uint64_t)row0 * NC);
        const float4* src = reinterpret_cast<const float4*>(smf);
        for (int i = tid; i < (BM * NC) / 4; i += 128) dst[i] = src[i];
    }

    // ================= handoff: 8th arriver scans this batch =================
    __threadfence();
    if (tid == 0) s_flag = (atomicAdd(&g_bcnt[batch], 1) == 7);
    __syncthreads();
    if (!s_flag) return;

    // ================= CRF scan phase (this CTA only) =================
    float* emx_s    = reinterpret_cast<float*>(usm);            // 43008 B
    float (*av)[24] = reinterpret_cast<float(*)[24]>(usm + 43008);
    float* red_f    = reinterpret_cast<float*>(usm + 43200);    // 512 B
    int*   red_i    = reinterpret_cast<int*>(usm + 43712);      // 512 B

    const float* emx_g = g_emx + batch * EM_STRIDE;

    // labels dtype detection (int32 vs int64; reads in-bounds for both)
    int ok = 1;
    for (int t = tid; t < SEQ; t += 128) {
        int v = labr[2 * t + 1];
        if (v != 0 && v != -1) ok = 0;
    }
    __syncthreads();   // epilogue smem use done before scan reuse
    int is64 = __syncthreads_and(ok);
    const int lbase = is64 ? batch * SEQ * 2 : batch * SEQ;
    const int lstep = is64 ? 2 : 1;
#define LAB(t) labr[lbase + (t) * lstep]

    for (int i = tid; i < (SEQ * NC) / 4; i += 128)
        reinterpret_cast<float4*>(emx_s)[i] =
            reinterpret_cast<const float4*>(emx_g)[i];

    // numerator (log2 domain) + valid length (mask is a prefix)
    float p = 0.f;
    int cnt = 0;
    for (int t = tid; t < SEQ; t += 128) {
        int l = LAB(t);
        if (l != -100) {
            cnt++;
            if (t == 0) {
                p += start_t[l] * L2E + fast_lg2(emx_g[l]);
            } else {
                int lp = LAB(t - 1);
                p += fast_lg2(emx_g[t * NC + l]) + trans[lp * NC + l] * L2E;
            }
        }
    }
    red_f[tid] = p;
    red_i[tid] = cnt;
    __syncthreads();
    for (int s = 64; s > 0; s >>= 1) {
        if (tid < s) { red_f[tid] += red_f[tid + s]; red_i[tid] += red_i[tid + s]; }
        __syncthreads();
    }
    if (tid == 0) {
        int len = red_i[0];
        s_len   = len;
        s_num2  = red_f[0] + end_t[LAB(len - 1)] * L2E;
    }
    __syncthreads();

    if (tid < 32) {
        const int j = lane < NC ? lane : NC - 1;
        float tl[24];
#pragma unroll
        for (int i = 0; i < NC; i++) tl[i] = fast_ex2(trans[i * NC + j] * L2E);
        tl[21] = tl[22] = tl[23] = 0.f;
        const float endx = fast_ex2(end_t[j] * L2E);

        float a = fast_ex2(start_t[j] * L2E) * emx_s[j];
        if (lane < NC)  av[0][lane] = a;
        if (lane >= NC && lane < 24) { av[0][lane] = 0.f; av[1][lane] = 0.f; }
        int offe = 0;
        int buf  = 0;
        const int len = s_len;

        for (int t = 1; t < len; t++) {
            float emn = emx_s[t * NC + j];   // hoisted off the serial path
            __syncwarp();
            const float4* vp = reinterpret_cast<const float4*>(av[buf]);
            float4 v0 = vp[0], v1 = vp[1], v2 = vp[2],
                   v3 = vp[3], v4 = vp[4], v5 = vp[5];
            int   e     = ((__float_as_int(v0.x) >> 23) & 255) - 127;
            float sclem = __int_as_float((127 - e) << 23) * emn;  // exact 2^-e
            offe += e;

            float s0 = v0.x * tl[0],  s1 = v0.y * tl[1],  s2 = v0.z * tl[2];
            float s3 = v0.w * tl[3],  s4 = v1.x * tl[4],  s5 = v1.y * tl[5];
            s0 += v1.z * tl[6];   s1 += v1.w * tl[7];   s2 += v2.x * tl[8];
            s3 += v2.y * tl[9];   s4 += v2.z * tl[10];  s5 += v2.w * tl[11];
            s0 += v3.x * tl[12];  s1 += v3.y * tl[13];  s2 += v3.z * tl[14];
            s3 += v3.w * tl[15];  s4 += v4.x * tl[16];  s5 += v4.y * tl[17];
            s0 += v4.z * tl[18];  s1 += v4.w * tl[19];  s2 += v5.x * tl[20];
            s3 += v5.y * tl[21];  s4 += v5.z * tl[22];  s5 += v5.w * tl[23];

            a = (((s0 + s1) + (s2 + s3)) + (s4 + s5)) * sclem;
            buf ^= 1;
            if (lane < NC) av[buf][lane] = a;
        }
        __syncwarp();

        float ex = (lane < NC) ? a * endx : 0.f;
#pragma unroll
        for (int d = 16; d > 0; d >>= 1)
            ex += __shfl_xor_sync(0xffffffffu, ex, d);
        if (lane == 0)
            g_res[batch] = (float)offe + fast_lg2(ex) - s_num2;
    }
#undef LAB

    // ================= final loss: 64th scanner reduces =================
    __syncthreads();
    __threadfence();
    if (tid == 0) {
        g_bcnt[batch] = 0;                       // reset for graph replay
        s_last = (atomicAdd(&g_done, 1) == BATCH - 1);
    }
    __syncthreads();
    if (s_last && tid < 32) {
        float v = g_res[tid] + g_res[tid + 32];
#pragma unroll
        for (int d = 16; d > 0; d >>= 1)
            v += __shfl_xor_sync(0xffffffffu, v, d);
        if (tid == 0) {
            out[0] = v * (1.0f / (64.0f * L2E));
            g_done = 0;                          // reset for graph replay
        }
    }
}

// ---------------------------------------------------------------------------
extern "C" void kernel_launch(void* const* d_in, const int* in_sizes, int n_in,
                              void* d_out, int out_size)
{
    const float* hidden = nullptr;
    const float* W      = nullptr;
    const float* trans  = nullptr;
    const int*   labels = nullptr;
    const float* small[3] = {nullptr, nullptr, nullptr};
    int nsmall = 0;

    for (int i = 0; i < n_in; i++) {
        switch (in_sizes[i]) {
            case BATCH * SEQ * HID: hidden = (const float*)d_in[i]; break;
            case HID * NC:          W      = (const float*)d_in[i]; break;
            case NC * NC:           trans  = (const float*)d_in[i]; break;
            case BATCH * SEQ:       labels = (const int*)d_in[i];   break;
            case NC: if (nsmall < 3) small[nsmall++] = (const float*)d_in[i]; break;
            default: break;
        }
    }
    const float* bias    = small[0];
    const float* start_t = small[1];
    const float* end_t   = small[2];

    pack_w_kernel<<<(NFRAG * 64 + 255) / 256, 256>>>(W);
    fused_kernel<<<512, 128>>>(hidden, bias, start_t, end_t, trans, labels,
                               (float*)d_out);
}

// round 14
// speedup vs baseline: 2.1130x; 1.1692x over previous
#include <cuda_runtime.h>
#include <cuda_bf16.h>
#include <cstdint>

#define L2E 1.4426950408889634f
#define BATCH 64
#define SEQ 512
#define HID 768
#define NC 21
#define EM_STRIDE (SEQ * NC)

#define BM 64
#define ASTRIDE 144           // bytes per bf16 A row in smem (64 bf16 + 8 pad)
#define NFRAG (12 * 4 * 3)    // k16-chunks x n8-tiles

__device__ __align__(16) float g_emx[BATCH * SEQ * NC];   // linear emissions 2^em2
__device__ __align__(16) uint32_t g_wfrag[NFRAG * 64];    // W bf16, mma-frag order
__device__ __align__(16) float g_half[BATCH][2][24];      // fwd/bwd half vectors
__device__ float g_hoffe[BATCH][2];                       // fwd/bwd exponent offsets
__device__ float g_num[BATCH];                            // numerators (log2)
__device__ float g_res[BATCH];
__device__ int g_bcnt[BATCH];   // gemm arrivals (roles); reset by role 7
__device__ int g_scnt[BATCH];   // publishes (num/bwd/fwd); reset by combiner
__device__ int g_done;          // combines; reset by final reducer

__device__ __forceinline__ float fast_ex2(float x) {
    float y; asm("ex2.approx.ftz.f32 %0, %1;" : "=f"(y) : "f"(x)); return y;
}
__device__ __forceinline__ float fast_lg2(float x) {
    float y; asm("lg2.approx.ftz.f32 %0, %1;" : "=f"(y) : "f"(x)); return y;
}
__device__ __forceinline__ uint32_t smem_u32(const void* p) {
    uint32_t a;
    asm("{ .reg .u64 t; cvta.to.shared.u64 t, %1; cvt.u32.u64 %0, t; }" : "=r"(a) : "l"(p));
    return a;
}
__device__ __forceinline__ void cp_async16(void* dst, const void* src) {
    unsigned d = (unsigned)__cvta_generic_to_shared(dst);
    asm volatile("cp.async.cg.shared.global [%0], [%1], 16;" :: "r"(d), "l"(src));
}

// ---------------------------------------------------------------------------
// Kernel 0: pack W into mma B-fragment order (proven in R10).
// ---------------------------------------------------------------------------
__global__ void pack_w_kernel(const float* __restrict__ W) {
    int o = blockIdx.x * blockDim.x + threadIdx.x;
    if (o >= NFRAG * 64) return;
    int h    = o & 1;
    int lane = (o >> 1) & 31;
    int f    = o >> 6;
    int nt   = f % 3;
    int kc   = f / 3;
    int k    = (kc >> 2) * 64 + (kc & 3) * 16 + (lane & 3) * 2 + h * 8;
    int n    = nt * 8 + (lane >> 2);
    float w0 = (n < NC) ? W[k * NC + n]       : 0.f;
    float w1 = (n < NC) ? W[(k + 1) * NC + n] : 0.f;
    uint32_t pk;
    asm("cvt.rn.satfinite.bf16x2.f32 %0, %1, %2;" : "=r"(pk) : "f"(w1), "f"(w0));
    g_wfrag[o] = pk;
}

// ---------------------------------------------------------------------------
// Fused kernel. After gemm, per-batch arrival roles: 5=numerator,
// 6=backward scan [mid,len), 7=forward scan [0,mid). Last of the 3
// publishers combines (logZ = fwd . bwd); 64th combiner reduces the loss.
// ---------------------------------------------------------------------------
#define USM_BYTES 44224
__global__ __launch_bounds__(128) void fused_kernel(
    const float* __restrict__ hidden,
    const float* __restrict__ bias,
    const float* __restrict__ start_t,
    const float* __restrict__ end_t,
    const float* __restrict__ trans,
    const int*   __restrict__ labr,
    float* __restrict__ out)
{
    __shared__ __align__(1024) uint8_t usm[USM_BYTES];
    __shared__ int s_role, s_len, s_pub, s_last;

    const int tid   = threadIdx.x;
    const int wid   = tid >> 5;
    const int lane  = tid & 31;
    const int row0  = blockIdx.x * BM;
    const int batch = blockIdx.x >> 3;

    // ================= GEMM phase (R13-proven) =================
    float*   f32s = reinterpret_cast<float*>(usm);      // 2 x 16KB ring
    uint8_t* tile = usm + 32768;                        // bf16 ldmatrix tile

    float acc[3][4];
#pragma unroll
    for (int i = 0; i < 3; i++)
#pragma unroll
        for (int j = 0; j < 4; j++) acc[i][j] = 0.f;

    auto issue = [&](int ch, int st) {
        const float* src0 = hidden + (uint64_t)row0 * HID + ch * 64;
#pragma unroll
        for (int u = 0; u < 8; u++) {
            int q = tid + u * 128;
            int r = q >> 4, seg = q & 15;
            cp_async16(&f32s[st * 4096 + q * 4], src0 + r * HID + seg * 4);
        }
        asm volatile("cp.async.commit_group;");
    };
    auto convert = [&](int st) {
#pragma unroll
        for (int u = 0; u < 8; u++) {
            int q = tid + u * 128;
            int r = q >> 4, seg = q & 15;
            float4 v = *reinterpret_cast<const float4*>(&f32s[st * 4096 + q * 4]);
            uint32_t b0, b1;
            asm("cvt.rn.satfinite.bf16x2.f32 %0, %1, %2;" : "=r"(b0) : "f"(v.y), "f"(v.x));
            asm("cvt.rn.satfinite.bf16x2.f32 %0, %1, %2;" : "=r"(b1) : "f"(v.w), "f"(v.z));
            uint2 pk = {b0, b1};
            *reinterpret_cast<uint2*>(tile + r * ASTRIDE + seg * 8) = pk;
        }
    };

    issue(0, 0);
    issue(1, 1);

    const int rowA = wid * 16 + (lane & 7) + ((lane >> 3) & 1) * 8;
    const int aoff = rowA * ASTRIDE + ((lane >> 4) * 16);

    for (int ch = 0; ch < 12; ch++) {
        if (ch < 11) asm volatile("cp.async.wait_group 1;");
        else         asm volatile("cp.async.wait_group 0;");
        __syncthreads();
        convert(ch & 1);
        __syncthreads();
        if (ch + 2 < 12) issue(ch + 2, ch & 1);

        const uint32_t abase = smem_u32(tile + aoff);
#pragma unroll
        for (int ksub = 0; ksub < 4; ksub++) {
            uint32_t a0, a1, a2, a3;
            asm volatile("ldmatrix.sync.aligned.m8n8.x4.shared.b16 {%0,%1,%2,%3}, [%4];"
                : "=r"(a0), "=r"(a1), "=r"(a2), "=r"(a3)
                : "r"(abase + ksub * 32));
            const int fbase = ((ch * 4 + ksub) * 3) * 64 + lane * 2;
#pragma unroll
            for (int nt = 0; nt < 3; nt++) {
                uint2 b = *reinterpret_cast<const uint2*>(&g_wfrag[fbase + nt * 64]);
                asm volatile("mma.sync.aligned.m16n8k16.row.col.f32.bf16.bf16.f32 "
                    "{%0,%1,%2,%3}, {%4,%5,%6,%7}, {%8,%9}, {%0,%1,%2,%3};"
                    : "+f"(acc[nt][0]), "+f"(acc[nt][1]), "+f"(acc[nt][2]), "+f"(acc[nt][3])
                    : "r"(a0), "r"(a1), "r"(a2), "r"(a3), "r"(b.x), "r"(b.y));
            }
        }
    }
    __syncthreads();

    // epilogue: frag -> emx -> smem -> coalesced store
    {
        float* smf = reinterpret_cast<float*>(usm);
        const int r0 = wid * 16 + (lane >> 2);
#pragma unroll
        for (int nt = 0; nt < 3; nt++) {
            int c = nt * 8 + (lane & 3) * 2;
            if (c < NC) {
                float bc = bias[c];
                smf[r0 * NC + c]       = fast_ex2((acc[nt][0] + bc) * L2E);
                smf[(r0 + 8) * NC + c] = fast_ex2((acc[nt][2] + bc) * L2E);
            }
            if (c + 1 < NC) {
                float bc = bias[c + 1];
                smf[r0 * NC + c + 1]       = fast_ex2((acc[nt][1] + bc) * L2E);
                smf[(r0 + 8) * NC + c + 1] = fast_ex2((acc[nt][3] + bc) * L2E);
            }
        }
        __syncthreads();
        float4* dst = reinterpret_cast<float4*>(g_emx + (uint64_t)row0 * NC);
        const float4* src = reinterpret_cast<const float4*>(smf);
        for (int i = tid; i < (BM * NC) / 4; i += 128) dst[i] = src[i];
    }

    // ================= role assignment =================
    __threadfence();
    if (tid == 0) s_role = atomicAdd(&g_bcnt[batch], 1);
    __syncthreads();
    const int role = s_role;
    if (role == 7 && tid == 0) g_bcnt[batch] = 0;   // all 8 arrived; replay-safe
    if (role < 5) return;

    // ================= labels: dtype + len (roles 5,6,7) =================
    float* red_f = reinterpret_cast<float*>(usm + 22016);
    int*   red_i = reinterpret_cast<int*>(usm + 22656);

    int okd = 1;
    for (int t = tid; t < SEQ; t += 128) {
        int v = labr[2 * t + 1];
        if (v != 0 && v != -1) okd = 0;
    }
    __syncthreads();
    int is64 = __syncthreads_and(okd);
    const int lbase = is64 ? batch * SEQ * 2 : batch * SEQ;
    const int lstep = is64 ? 2 : 1;
#define LAB(t) labr[lbase + (t) * lstep]
    {
        int cnt = 0;
        for (int t = tid; t < SEQ; t += 128)
            if (LAB(t) != -100) cnt++;
        red_i[tid] = cnt;
        __syncthreads();
        for (int s = 64; s > 0; s >>= 1) {
            if (tid < s) red_i[tid] += red_i[tid + s];
            __syncthreads();
        }
        if (tid == 0) s_len = red_i[0];
        __syncthreads();
    }
    const int len = s_len;
    const int mid = (len + 1) >> 1;       // len>=256 so both halves nonempty
    const float* emx_g = g_emx + batch * EM_STRIDE;

    float* emx_s    = reinterpret_cast<float*>(usm);              // <=21504 B
    float (*av)[24] = reinterpret_cast<float(*)[24]>(usm + 21504);

    if (role == 5) {
        // ---------- numerator (log2 domain) ----------
        float pa = 0.f;
        for (int t = tid; t < SEQ; t += 128) {
            int l = LAB(t);
            if (l != -100) {
                if (t == 0) {
                    pa += start_t[l] * L2E + fast_lg2(emx_g[l]);
                } else {
                    int lp = LAB(t - 1);
                    pa += fast_lg2(emx_g[t * NC + l]) + trans[lp * NC + l] * L2E;
                }
            }
        }
        red_f[tid] = pa;
        __syncthreads();
        for (int s = 64; s > 0; s >>= 1) {
            if (tid < s) red_f[tid] += red_f[tid + s];
            __syncthreads();
        }
        if (tid == 0)
            g_num[batch] = red_f[0] + end_t[LAB(len - 1)] * L2E;
    } else if (role == 7) {
        // ---------- forward scan: alpha over [0, mid) ----------
        for (int i = tid; i < mid * NC; i += 128) emx_s[i] = emx_g[i];
        __syncthreads();
        if (tid < 32) {
            const int j = lane < NC ? lane : NC - 1;
            float tl[24];
#pragma unroll
            for (int i = 0; i < NC; i++) tl[i] = fast_ex2(trans[i * NC + j] * L2E);
            tl[21] = tl[22] = tl[23] = 0.f;

            float a = fast_ex2(start_t[j] * L2E) * emx_s[j];
            if (lane < NC)  av[0][lane] = a;
            if (lane >= NC && lane < 24) { av[0][lane] = 0.f; av[1][lane] = 0.f; }
            int offe = 0, buf = 0;
            for (int t = 1; t < mid; t++) {
                float emn = emx_s[t * NC + j];
                __syncwarp();
                const float4* vp = reinterpret_cast<const float4*>(av[buf]);
                float4 v0 = vp[0], v1 = vp[1], v2 = vp[2],
                       v3 = vp[3], v4 = vp[4], v5 = vp[5];
                int   e     = ((__float_as_int(v0.x) >> 23) & 255) - 127;
                float sclem = __int_as_float((127 - e) << 23) * emn;
                offe += e;
                float s0 = v0.x * tl[0],  s1 = v0.y * tl[1],  s2 = v0.z * tl[2];
                float s3 = v0.w * tl[3],  s4 = v1.x * tl[4],  s5 = v1.y * tl[5];
                s0 += v1.z * tl[6];   s1 += v1.w * tl[7];   s2 += v2.x * tl[8];
                s3 += v2.y * tl[9];   s4 += v2.z * tl[10];  s5 += v2.w * tl[11];
                s0 += v3.x * tl[12];  s1 += v3.y * tl[13];  s2 += v3.z * tl[14];
                s3 += v3.w * tl[15];  s4 += v4.x * tl[16];  s5 += v4.y * tl[17];
                s0 += v4.z * tl[18];  s1 += v4.w * tl[19];  s2 += v5.x * tl[20];
                s3 += v5.y * tl[21];  s4 += v5.z * tl[22];  s5 += v5.w * tl[23];
                a = (((s0 + s1) + (s2 + s3)) + (s4 + s5)) * sclem;
                buf ^= 1;
                if (lane < NC) av[buf][lane] = a;
            }
            __syncwarp();
            if (lane < 24) g_half[batch][0][lane] = (lane < NC) ? a : 0.f;
            if (lane == 0) g_hoffe[batch][0] = (float)offe;
        }
    } else {
        // ---------- backward scan: beta over [mid, len) ----------
        const int nrows = len - mid;
        for (int i = tid; i < nrows * NC; i += 128)
            emx_s[i] = emx_g[mid * NC + i];
        __syncthreads();
        if (tid < 32) {
            const int j = lane < NC ? lane : NC - 1;
            float tb[24];                   // row j of T (linear)
#pragma unroll
            for (int k = 0; k < NC; k++) tb[k] = fast_ex2(trans[j * NC + k] * L2E);
            tb[21] = tb[22] = tb[23] = 0.f;

            float b = fast_ex2(end_t[j] * L2E);   // beta_{len-1}
            int offe = 0, buf = 0;
            if (lane >= NC && lane < 24) { av[0][lane] = 0.f; av[1][lane] = 0.f; }
            for (int t = len - 1; t >= mid; t--) {
                float d = b * emx_s[(t - mid) * NC + j];
                if (lane < NC) av[buf][lane] = d;
                __syncwarp();
                const float4* vp = reinterpret_cast<const float4*>(av[buf]);
                float4 v0 = vp[0], v1 = vp[1], v2 = vp[2],
                       v3 = vp[3], v4 = vp[4], v5 = vp[5];
                int   e   = ((__float_as_int(v0.x) >> 23) & 255) - 127;
                float scl = __int_as_float((127 - e) << 23);
                offe += e;
                float s0 = v0.x * tb[0],  s1 = v0.y * tb[1],  s2 = v0.z * tb[2];
                float s3 = v0.w * tb[3],  s4 = v1.x * tb[4],  s5 = v1.y * tb[5];
                s0 += v1.z * tb[6];   s1 += v1.w * tb[7];   s2 += v2.x * tb[8];
                s3 += v2.y * tb[9];   s4 += v2.z * tb[10];  s5 += v2.w * tb[11];
                s0 += v3.x * tb[12];  s1 += v3.y * tb[13];  s2 += v3.z * tb[14];
                s3 += v3.w * tb[15];  s4 += v4.x * tb[16];  s5 += v4.y * tb[17];
                s0 += v4.z * tb[18];  s1 += v4.w * tb[19];  s2 += v5.x * tb[20];
                s3 += v5.y * tb[21];  s4 += v5.z * tb[22];  s5 += v5.w * tb[23];
                b = (((s0 + s1) + (s2 + s3)) + (s4 + s5)) * scl;
                buf ^= 1;
            }
            __syncwarp();
            if (lane < 24) g_half[batch][1][lane] = (lane < NC) ? b : 0.f;
            if (lane == 0) g_hoffe[batch][1] = (float)offe;
        }
    }
#undef LAB

    // ================= combine: last of 3 publishers =================
    __syncthreads();
    __threadfence();
    if (tid == 0) s_pub = atomicAdd(&g_scnt[batch], 1);
    __syncthreads();
    if (s_pub != 2) return;
    __threadfence();
    if (tid == 0) g_scnt[batch] = 0;                 // replay-safe

    if (tid < 32) {
        float ex = (lane < NC) ? g_half[batch][0][lane] * g_half[batch][1][lane] : 0.f;
#pragma unroll
        for (int d = 16; d > 0; d >>= 1)
            ex += __shfl_xor_sync(0xffffffffu, ex, d);
        if (lane == 0)
            g_res[batch] = g_hoffe[batch][0] + g_hoffe[batch][1] +
                           fast_lg2(ex) - g_num[batch];
    }

    // ================= final loss: 64th combiner reduces =================
    __syncthreads();
    __threadfence();
    if (tid == 0) s_last = (atomicAdd(&g_done, 1) == BATCH - 1);
    __syncthreads();
    if (s_last && tid < 32) {
        float v = g_res[tid] + g_res[tid + 32];
#pragma unroll
        for (int d = 16; d > 0; d >>= 1)
            v += __shfl_xor_sync(0xffffffffu, v, d);
        if (tid == 0) {
            out[0] = v * (1.0f / (64.0f * L2E));
            g_done = 0;                              // replay-safe
        }
    }
}

// ---------------------------------------------------------------------------
extern "C" void kernel_launch(void* const* d_in, const int* in_sizes, int n_in,
                              void* d_out, int out_size)
{
    const float* hidden = nullptr;
    const float* W      = nullptr;
    const float* trans  = nullptr;
    const int*   labels = nullptr;
    const float* small[3] = {nullptr, nullptr, nullptr};
    int nsmall = 0;

    for (int i = 0; i < n_in; i++) {
        switch (in_sizes[i]) {
            case BATCH * SEQ * HID: hidden = (const float*)d_in[i]; break;
            case HID * NC:          W      = (const float*)d_in[i]; break;
            case NC * NC:           trans  = (const float*)d_in[i]; break;
            case BATCH * SEQ:       labels = (const int*)d_in[i];   break;
            case NC: if (nsmall < 3) small[nsmall++] = (const float*)d_in[i]; break;
            default: break;
        }
    }
    const float* bias    = small[0];
    const float* start_t = small[1];
    const float* end_t   = small[2];

    pack_w_kernel<<<(NFRAG * 64 + 255) / 256, 256>>>(W);
    fused_kernel<<<512, 128>>>(hidden, bias, start_t, end_t, trans, labels,
                               (float*)d_out);
}

// round 15
// speedup vs baseline: 2.1801x; 1.0317x over previous
#include <cuda_runtime.h>
#include <cuda_bf16.h>
#include <cstdint>

#define L2E 1.4426950408889634f
#define BATCH 64
#define SEQ 512
#define HID 768
#define NC 21
#define EM_STRIDE (SEQ * NC)

#define BM 64
#define ASTRIDE 144           // bytes per bf16 A row in smem (64 bf16 + 8 pad)
#define NFRAG (12 * 4 * 3)    // k16-chunks x n8-tiles

__device__ __align__(16) float g_emx[BATCH * SEQ * NC];   // linear emissions 2^em2
__device__ __align__(16) uint32_t g_wfrag[NFRAG * 64];    // W bf16, mma-frag order
__device__ __align__(16) float g_half[BATCH][2][24];      // fwd/bwd half vectors
__device__ float g_hoffe[BATCH][2];                       // fwd/bwd exponent offsets
__device__ float g_num[BATCH];                            // numerators (log2)
__device__ float g_res[BATCH];
__device__ int g_bcnt[BATCH];   // gemm arrivals (roles); reset by role 7
__device__ int g_scnt[BATCH];   // publishes (num/bwd/fwd); reset by combiner
__device__ int g_done;          // combines; reset by final reducer

__device__ __forceinline__ float fast_ex2(float x) {
    float y; asm("ex2.approx.ftz.f32 %0, %1;" : "=f"(y) : "f"(x)); return y;
}
__device__ __forceinline__ float fast_lg2(float x) {
    float y; asm("lg2.approx.ftz.f32 %0, %1;" : "=f"(y) : "f"(x)); return y;
}
__device__ __forceinline__ uint32_t smem_u32(const void* p) {
    uint32_t a;
    asm("{ .reg .u64 t; cvta.to.shared.u64 t, %1; cvt.u32.u64 %0, t; }" : "=r"(a) : "l"(p));
    return a;
}
__device__ __forceinline__ void cp_async16(void* dst, const void* src) {
    unsigned d = (unsigned)__cvta_generic_to_shared(dst);
    asm volatile("cp.async.cg.shared.global [%0], [%1], 16;" :: "r"(d), "l"(src));
}

// ---------------------------------------------------------------------------
// Kernel 0: pack W into mma B-fragment order (proven in R10).
// ---------------------------------------------------------------------------
__global__ void pack_w_kernel(const float* __restrict__ W) {
    int o = blockIdx.x * blockDim.x + threadIdx.x;
    if (o >= NFRAG * 64) return;
    int h    = o & 1;
    int lane = (o >> 1) & 31;
    int f    = o >> 6;
    int nt   = f % 3;
    int kc   = f / 3;
    int k    = (kc >> 2) * 64 + (kc & 3) * 16 + (lane & 3) * 2 + h * 8;
    int n    = nt * 8 + (lane >> 2);
    float w0 = (n < NC) ? W[k * NC + n]       : 0.f;
    float w1 = (n < NC) ? W[(k + 1) * NC + n] : 0.f;
    uint32_t pk;
    asm("cvt.rn.satfinite.bf16x2.f32 %0, %1, %2;" : "=r"(pk) : "f"(w1), "f"(w0));
    g_wfrag[o] = pk;
}

// ---------------------------------------------------------------------------
// Fused kernel. R15 gemm: per-warp cp.async pipeline, conversion, and mma —
// warp w owns rows [16w,16w+16) end to end, so the mainloop has ZERO CTA
// barriers (cp.async.wait_group is per-thread; smem rows are warp-private;
// within-warp smem ordering is program order). Scan side = R14 (proven):
// roles 5=numerator, 6=backward half-scan, 7=forward half-scan; last
// publisher combines, 64th combiner reduces the loss.
// ---------------------------------------------------------------------------
#define USM_BYTES 44224
__global__ __launch_bounds__(128) void fused_kernel(
    const float* __restrict__ hidden,
    const float* __restrict__ bias,
    const float* __restrict__ start_t,
    const float* __restrict__ end_t,
    const float* __restrict__ trans,
    const int*   __restrict__ labr,
    float* __restrict__ out)
{
    __shared__ __align__(1024) uint8_t usm[USM_BYTES];
    __shared__ int s_role, s_len, s_pub, s_last;

    const int tid   = threadIdx.x;
    const int wid   = tid >> 5;
    const int lane  = tid & 31;
    const int row0  = blockIdx.x * BM;
    const int batch = blockIdx.x >> 3;

    // ================= GEMM phase (barrier-free mainloop) =================
    float*   f32s = reinterpret_cast<float*>(usm);      // 2 x 16KB fp32 ring
    uint8_t* tile = usm + 32768;                        // bf16 ldmatrix tile

    float acc[3][4];
#pragma unroll
    for (int i = 0; i < 3; i++)
#pragma unroll
        for (int j = 0; j < 4; j++) acc[i][j] = 0.f;

    // warp-private: 16 rows x 64 cols per stage
    auto issue = [&](int ch, int st) {
        const float* src0 = hidden + (uint64_t)(row0 + wid * 16) * HID + ch * 64;
#pragma unroll
        for (int u = 0; u < 8; u++) {
            int q = lane + u * 32;            // 0..255 (16B segs of 16 rows)
            int r = q >> 4, seg = q & 15;
            cp_async16(&f32s[st * 4096 + (wid * 16 + r) * 64 + seg * 4],
                       src0 + r * HID + seg * 4);
        }
        asm volatile("cp.async.commit_group;");
    };
    auto convert = [&](int st) {
#pragma unroll
        for (int u = 0; u < 8; u++) {
            int q = lane + u * 32;
            int r = q >> 4, seg = q & 15;
            int rr = wid * 16 + r;
            float4 v = *reinterpret_cast<const float4*>(
                &f32s[st * 4096 + rr * 64 + seg * 4]);
            uint32_t b0, b1;
            asm("cvt.rn.satfinite.bf16x2.f32 %0, %1, %2;" : "=r"(b0) : "f"(v.y), "f"(v.x));
            asm("cvt.rn.satfinite.bf16x2.f32 %0, %1, %2;" : "=r"(b1) : "f"(v.w), "f"(v.z));
            uint2 pk = {b0, b1};
            *reinterpret_cast<uint2*>(tile + rr * ASTRIDE + seg * 8) = pk;
        }
    };

    issue(0, 0);
    issue(1, 1);

    const int rowA = wid * 16 + (lane & 7) + ((lane >> 3) & 1) * 8;
    const int aoff = rowA * ASTRIDE + ((lane >> 4) * 16);

    for (int ch = 0; ch < 12; ch++) {
        if (ch < 11) asm volatile("cp.async.wait_group 1;");
        else         asm volatile("cp.async.wait_group 0;");
        convert(ch & 1);                       // own rows: no barrier needed
        if (ch + 2 < 12) issue(ch + 2, ch & 1);

        const uint32_t abase = smem_u32(tile + aoff);
#pragma unroll
        for (int ksub = 0; ksub < 4; ksub++) {
            uint32_t a0, a1, a2, a3;
            asm volatile("ldmatrix.sync.aligned.m8n8.x4.shared.b16 {%0,%1,%2,%3}, [%4];"
                : "=r"(a0), "=r"(a1), "=r"(a2), "=r"(a3)
                : "r"(abase + ksub * 32));
            const int fbase = ((ch * 4 + ksub) * 3) * 64 + lane * 2;
#pragma unroll
            for (int nt = 0; nt < 3; nt++) {
                uint2 b = *reinterpret_cast<const uint2*>(&g_wfrag[fbase + nt * 64]);
                asm volatile("mma.sync.aligned.m16n8k16.row.col.f32.bf16.bf16.f32 "
                    "{%0,%1,%2,%3}, {%4,%5,%6,%7}, {%8,%9}, {%0,%1,%2,%3};"
                    : "+f"(acc[nt][0]), "+f"(acc[nt][1]), "+f"(acc[nt][2]), "+f"(acc[nt][3])
                    : "r"(a0), "r"(a1), "r"(a2), "r"(a3), "r"(b.x), "r"(b.y));
            }
        }
    }
    __syncthreads();   // all warps done with usm before epilogue reuse

    // epilogue: frag -> emx -> smem -> coalesced store
    {
        float* smf = reinterpret_cast<float*>(usm);
        const int r0 = wid * 16 + (lane >> 2);
#pragma unroll
        for (int nt = 0; nt < 3; nt++) {
            int c = nt * 8 + (lane & 3) * 2;
            if (c < NC) {
                float bc = bias[c];
                smf[r0 * NC + c]       = fast_ex2((acc[nt][0] + bc) * L2E);
                smf[(r0 + 8) * NC + c] = fast_ex2((acc[nt][2] + bc) * L2E);
            }
            if (c + 1 < NC) {
                float bc = bias[c + 1];
                smf[r0 * NC + c + 1]       = fast_ex2((acc[nt][1] + bc) * L2E);
                smf[(r0 + 8) * NC + c + 1] = fast_ex2((acc[nt][3] + bc) * L2E);
            }
        }
        __syncthreads();
        float4* dst = reinterpret_cast<float4*>(g_emx + (uint64_t)row0 * NC);
        const float4* src = reinterpret_cast<const float4*>(smf);
        for (int i = tid; i < (BM * NC) / 4; i += 128) dst[i] = src[i];
    }

    // ================= role assignment =================
    __threadfence();
    if (tid == 0) s_role = atomicAdd(&g_bcnt[batch], 1);
    __syncthreads();
    const int role = s_role;
    if (role == 7 && tid == 0) g_bcnt[batch] = 0;   // all 8 arrived; replay-safe
    if (role < 5) return;

    // ================= labels: dtype + len (roles 5,6,7) =================
    float* red_f = reinterpret_cast<float*>(usm + 22016);
    int*   red_i = reinterpret_cast<int*>(usm + 22656);

    int okd = 1;
    for (int t = tid; t < SEQ; t += 128) {
        int v = labr[2 * t + 1];
        if (v != 0 && v != -1) okd = 0;
    }
    __syncthreads();
    int is64 = __syncthreads_and(okd);
    const int lbase = is64 ? batch * SEQ * 2 : batch * SEQ;
    const int lstep = is64 ? 2 : 1;
#define LAB(t) labr[lbase + (t) * lstep]
    {
        int cnt = 0;
        for (int t = tid; t < SEQ; t += 128)
            if (LAB(t) != -100) cnt++;
        red_i[tid] = cnt;
        __syncthreads();
        for (int s = 64; s > 0; s >>= 1) {
            if (tid < s) red_i[tid] += red_i[tid + s];
            __syncthreads();
        }
        if (tid == 0) s_len = red_i[0];
        __syncthreads();
    }
    const int len = s_len;
    const int mid = (len + 1) >> 1;       // len>=256 so both halves nonempty
    const float* emx_g = g_emx + batch * EM_STRIDE;

    float* emx_s    = reinterpret_cast<float*>(usm);              // <=21504 B
    float (*av)[24] = reinterpret_cast<float(*)[24]>(usm + 21504);

    if (role == 5) {
        // ---------- numerator (log2 domain) ----------
        float pa = 0.f;
        for (int t = tid; t < SEQ; t += 128) {
            int l = LAB(t);
            if (l != -100) {
                if (t == 0) {
                    pa += start_t[l] * L2E + fast_lg2(emx_g[l]);
                } else {
                    int lp = LAB(t - 1);
                    pa += fast_lg2(emx_g[t * NC + l]) + trans[lp * NC + l] * L2E;
                }
            }
        }
        red_f[tid] = pa;
        __syncthreads();
        for (int s = 64; s > 0; s >>= 1) {
            if (tid < s) red_f[tid] += red_f[tid + s];
            __syncthreads();
        }
        if (tid == 0)
            g_num[batch] = red_f[0] + end_t[LAB(len - 1)] * L2E;
    } else if (role == 7) {
        // ---------- forward scan: alpha over [0, mid) ----------
        for (int i = tid; i < mid * NC; i += 128) emx_s[i] = emx_g[i];
        __syncthreads();
        if (tid < 32) {
            const int j = lane < NC ? lane : NC - 1;
            float tl[24];
#pragma unroll
            for (int i = 0; i < NC; i++) tl[i] = fast_ex2(trans[i * NC + j] * L2E);
            tl[21] = tl[22] = tl[23] = 0.f;

            float a = fast_ex2(start_t[j] * L2E) * emx_s[j];
            if (lane < NC)  av[0][lane] = a;
            if (lane >= NC && lane < 24) { av[0][lane] = 0.f; av[1][lane] = 0.f; }
            int offe = 0, buf = 0;
            for (int t = 1; t < mid; t++) {
                float emn = emx_s[t * NC + j];
                __syncwarp();
                const float4* vp = reinterpret_cast<const float4*>(av[buf]);
                float4 v0 = vp[0], v1 = vp[1], v2 = vp[2],
                       v3 = vp[3], v4 = vp[4], v5 = vp[5];
                int   e     = ((__float_as_int(v0.x) >> 23) & 255) - 127;
                float sclem = __int_as_float((127 - e) << 23) * emn;
                offe += e;
                float s0 = v0.x * tl[0],  s1 = v0.y * tl[1],  s2 = v0.z * tl[2];
                float s3 = v0.w * tl[3],  s4 = v1.x * tl[4],  s5 = v1.y * tl[5];
                s0 += v1.z * tl[6];   s1 += v1.w * tl[7];   s2 += v2.x * tl[8];
                s3 += v2.y * tl[9];   s4 += v2.z * tl[10];  s5 += v2.w * tl[11];
                s0 += v3.x * tl[12];  s1 += v3.y * tl[13];  s2 += v3.z * tl[14];
                s3 += v3.w * tl[15];  s4 += v4.x * tl[16];  s5 += v4.y * tl[17];
                s0 += v4.z * tl[18];  s1 += v4.w * tl[19];  s2 += v5.x * tl[20];
                s3 += v5.y * tl[21];  s4 += v5.z * tl[22];  s5 += v5.w * tl[23];
                a = (((s0 + s1) + (s2 + s3)) + (s4 + s5)) * sclem;
                buf ^= 1;
                if (lane < NC) av[buf][lane] = a;
            }
            __syncwarp();
            if (lane < 24) g_half[batch][0][lane] = (lane < NC) ? a : 0.f;
            if (lane == 0) g_hoffe[batch][0] = (float)offe;
        }
    } else {
        // ---------- backward scan: beta over [mid, len) ----------
        const int nrows = len - mid;
        for (int i = tid; i < nrows * NC; i += 128)
            emx_s[i] = emx_g[mid * NC + i];
        __syncthreads();
        if (tid < 32) {
            const int j = lane < NC ? lane : NC - 1;
            float tb[24];                   // row j of T (linear)
#pragma unroll
            for (int k = 0; k < NC; k++) tb[k] = fast_ex2(trans[j * NC + k] * L2E);
            tb[21] = tb[22] = tb[23] = 0.f;

            float b = fast_ex2(end_t[j] * L2E);   // beta_{len-1}
            int offe = 0, buf = 0;
            if (lane >= NC && lane < 24) { av[0][lane] = 0.f; av[1][lane] = 0.f; }
            for (int t = len - 1; t >= mid; t--) {
                float d = b * emx_s[(t - mid) * NC + j];
                if (lane < NC) av[buf][lane] = d;
                __syncwarp();
                const float4* vp = reinterpret_cast<const float4*>(av[buf]);
                float4 v0 = vp[0], v1 = vp[1], v2 = vp[2],
                       v3 = vp[3], v4 = vp[4], v5 = vp[5];
                int   e   = ((__float_as_int(v0.x) >> 23) & 255) - 127;
                float scl = __int_as_float((127 - e) << 23);
                offe += e;
                float s0 = v0.x * tb[0],  s1 = v0.y * tb[1],  s2 = v0.z * tb[2];
                float s3 = v0.w * tb[3],  s4 = v1.x * tb[4],  s5 = v1.y * tb[5];
                s0 += v1.z * tb[6];   s1 += v1.w * tb[7];   s2 += v2.x * tb[8];
                s3 += v2.y * tb[9];   s4 += v2.z * tb[10];  s5 += v2.w * tb[11];
                s0 += v3.x * tb[12];  s1 += v3.y * tb[13];  s2 += v3.z * tb[14];
                s3 += v3.w * tb[15];  s4 += v4.x * tb[16];  s5 += v4.y * tb[17];
                s0 += v4.z * tb[18];  s1 += v4.w * tb[19];  s2 += v5.x * tb[20];
                s3 += v5.y * tb[21];  s4 += v5.z * tb[22];  s5 += v5.w * tb[23];
                b = (((s0 + s1) + (s2 + s3)) + (s4 + s5)) * scl;
                buf ^= 1;
            }
            __syncwarp();
            if (lane < 24) g_half[batch][1][lane] = (lane < NC) ? b : 0.f;
            if (lane == 0) g_hoffe[batch][1] = (float)offe;
        }
    }
#undef LAB

    // ================= combine: last of 3 publishers =================
    __syncthreads();
    __threadfence();
    if (tid == 0) s_pub = atomicAdd(&g_scnt[batch], 1);
    __syncthreads();
    if (s_pub != 2) return;
    __threadfence();
    if (tid == 0) g_scnt[batch] = 0;                 // replay-safe

    if (tid < 32) {
        float ex = (lane < NC) ? g_half[batch][0][lane] * g_half[batch][1][lane] : 0.f;
#pragma unroll
        for (int d = 16; d > 0; d >>= 1)
            ex += __shfl_xor_sync(0xffffffffu, ex, d);
        if (lane == 0)
            g_res[batch] = g_hoffe[batch][0] + g_hoffe[batch][1] +
                           fast_lg2(ex) - g_num[batch];
    }

    // ================= final loss: 64th combiner reduces =================
    __syncthreads();
    __threadfence();
    if (tid == 0) s_last = (atomicAdd(&g_done, 1) == BATCH - 1);
    __syncthreads();
    if (s_last && tid < 32) {
        float v = g_res[tid] + g_res[tid + 32];
#pragma unroll
        for (int d = 16; d > 0; d >>= 1)
            v += __shfl_xor_sync(0xffffffffu, v, d);
        if (tid == 0) {
            out[0] = v * (1.0f / (64.0f * L2E));
            g_done = 0;                              // replay-safe
        }
    }
}

// ---------------------------------------------------------------------------
extern "C" void kernel_launch(void* const* d_in, const int* in_sizes, int n_in,
                              void* d_out, int out_size)
{
    const float* hidden = nullptr;
    const float* W      = nullptr;
    const float* trans  = nullptr;
    const int*   labels = nullptr;
    const float* small[3] = {nullptr, nullptr, nullptr};
    int nsmall = 0;

    for (int i = 0; i < n_in; i++) {
        switch (in_sizes[i]) {
            case BATCH * SEQ * HID: hidden = (const float*)d_in[i]; break;
            case HID * NC:          W      = (const float*)d_in[i]; break;
            case NC * NC:           trans  = (const float*)d_in[i]; break;
            case BATCH * SEQ:       labels = (const int*)d_in[i];   break;
            case NC: if (nsmall < 3) small[nsmall++] = (const float*)d_in[i]; break;
            default: break;
        }
    }
    const float* bias    = small[0];
    const float* start_t = small[1];
    const float* end_t   = small[2];

    pack_w_kernel<<<(NFRAG * 64 + 255) / 256, 256>>>(W);
    fused_kernel<<<512, 128>>>(hidden, bias, start_t, end_t, trans, labels,
                               (float*)d_out);
}

// round 16
// speedup vs baseline: 2.3228x; 1.0654x over previous
#include <cuda_runtime.h>
#include <cuda_bf16.h>
#include <cstdint>

#define L2E 1.4426950408889634f
#define BATCH 64
#define SEQ 512
#define HID 768
#define NC 21
#define EM_STRIDE (SEQ * NC)

#define BM 64
#define ASTRIDE 144           // bytes per bf16 A row in smem (64 bf16 + 8 pad)
#define NFRAG (12 * 4 * 3)    // k16 tiles x n8 tiles = 144 B-fragments

__device__ __align__(16) float g_emx[BATCH * SEQ * NC];   // linear emissions 2^em2
__device__ __align__(16) uint32_t g_wfrag[NFRAG * 64];    // W bf16, mma-frag order
__device__ __align__(16) float g_half[BATCH][2][24];      // fwd/bwd half vectors
__device__ float g_hoffe[BATCH][2];                       // fwd/bwd exponent offsets
__device__ float g_num[BATCH];                            // numerators (log2)
__device__ float g_res[BATCH];
__device__ int g_bcnt[BATCH];   // gemm arrivals (roles); reset by role 7
__device__ int g_scnt[BATCH];   // publishes (num/bwd/fwd); reset by combiner
__device__ int g_done;          // combines; reset by final reducer

__device__ __forceinline__ float fast_ex2(float x) {
    float y; asm("ex2.approx.ftz.f32 %0, %1;" : "=f"(y) : "f"(x)); return y;
}
__device__ __forceinline__ float fast_lg2(float x) {
    float y; asm("lg2.approx.ftz.f32 %0, %1;" : "=f"(y) : "f"(x)); return y;
}
__device__ __forceinline__ uint32_t smem_u32(const void* p) {
    uint32_t a;
    asm("{ .reg .u64 t; cvta.to.shared.u64 t, %1; cvt.u32.u64 %0, t; }" : "=r"(a) : "l"(p));
    return a;
}
__device__ __forceinline__ void cp_async16(void* dst, const void* src) {
    unsigned d = (unsigned)__cvta_generic_to_shared(dst);
    asm volatile("cp.async.cg.shared.global [%0], [%1], 16;" :: "r"(d), "l"(src));
}
#define PACK2(d, lo, hi) asm("mov.b64 %0, {%1, %2};" : "=l"(d) : "f"(lo), "f"(hi))
#define MUL2(d, a, b)    asm("mul.rn.f32x2 %0, %1, %2;" : "=l"(d) : "l"(a), "l"(b))
#define FMA2(d, a, b)    asm("fma.rn.f32x2 %0, %1, %2, %3;" : "=l"(d) : "l"(a), "l"(b), "l"(d))
#define ADD2(d, a, b)    asm("add.rn.f32x2 %0, %1, %2;" : "=l"(d) : "l"(a), "l"(b))
#define UNPACK2(lo, hi, s) asm("mov.b64 {%0, %1}, %2;" : "=f"(lo), "=f"(hi) : "l"(s))

// ---------------------------------------------------------------------------
// Kernel 0: pack W into mma B-fragment order (proven in R10).
// ---------------------------------------------------------------------------
__global__ void pack_w_kernel(const float* __restrict__ W) {
    int o = blockIdx.x * blockDim.x + threadIdx.x;
    if (o >= NFRAG * 64) return;
    int h    = o & 1;
    int lane = (o >> 1) & 31;
    int f    = o >> 6;
    int nt   = f % 3;
    int kc   = f / 3;
    int k    = kc * 16 + (lane & 3) * 2 + h * 8;
    int n    = nt * 8 + (lane >> 2);
    float w0 = (n < NC) ? W[k * NC + n]       : 0.f;
    float w1 = (n < NC) ? W[(k + 1) * NC + n] : 0.f;
    uint32_t pk;
    asm("cvt.rn.satfinite.bf16x2.f32 %0, %1, %2;" : "=r"(pk) : "f"(w1), "f"(w0));
    g_wfrag[o] = pk;
}

// matvec step in f32x2: 12 FFMA2 on 2 chains instead of 48 scalar FMAs.
// u0..u5 hold 24 floats (12 pairs); m2[12] the column pairs.
#define MATVEC2(RES, u0, u1, u2, m2) do {                                   \
    uint64_t _a0, _a1;                                                       \
    MUL2(_a0, u0.x, m2[0]);  MUL2(_a1, u0.y, m2[1]);                         \
    FMA2(_a0, u1.x, m2[2]);  FMA2(_a1, u1.y, m2[3]);                         \
    FMA2(_a0, u2.x, m2[4]);  FMA2(_a1, u2.y, m2[5]);                         \
    FMA2(_a0, u3.x, m2[6]);  FMA2(_a1, u3.y, m2[7]);                         \
    FMA2(_a0, u4.x, m2[8]);  FMA2(_a1, u4.y, m2[9]);                         \
    FMA2(_a0, u5.x, m2[10]); FMA2(_a1, u5.y, m2[11]);                        \
    ADD2(_a0, _a0, _a1);                                                     \
    float _lo, _hi; UNPACK2(_lo, _hi, _a0);                                  \
    RES = _lo + _hi;                                                         \
} while (0)

// ---------------------------------------------------------------------------
// Fused kernel. Gemm: per-warp 4-deep cp.async ring of 32-col chunks (no CTA
// barriers in the mainloop; warp w owns rows [16w,16w+16) end to end).
// Scan roles (by gemm arrival): 5=numerator, 6=backward half, 7=forward half;
// last publisher combines, 64th combiner reduces the loss.
// ---------------------------------------------------------------------------
#define USM_BYTES 44224
__global__ __launch_bounds__(128) void fused_kernel(
    const float* __restrict__ hidden,
    const float* __restrict__ bias,
    const float* __restrict__ start_t,
    const float* __restrict__ end_t,
    const float* __restrict__ trans,
    const int*   __restrict__ labr,
    float* __restrict__ out)
{
    __shared__ __align__(1024) uint8_t usm[USM_BYTES];
    __shared__ int s_role, s_len, s_pub, s_last;

    const int tid   = threadIdx.x;
    const int wid   = tid >> 5;
    const int lane  = tid & 31;
    const int row0  = blockIdx.x * BM;
    const int batch = blockIdx.x >> 3;

    // ================= GEMM phase =================
    // fp32 ring: 4 stages x 8KB (64 rows x 32 cols) at usm; bf16 tile at +32768
    float*   f32s = reinterpret_cast<float*>(usm);
    uint8_t* tile = usm + 32768;

    float acc[3][4];
#pragma unroll
    for (int i = 0; i < 3; i++)
#pragma unroll
        for (int j = 0; j < 4; j++) acc[i][j] = 0.f;

    // 24 chunks of 32 cols; warp part = 16 rows x 32 cols = 2KB per stage
    auto issue = [&](int ch, int st) {
        const float* src0 = hidden + (uint64_t)(row0 + wid * 16) * HID + ch * 32;
#pragma unroll
        for (int u = 0; u < 4; u++) {
            int q = lane + u * 32;            // 0..127
            int r = q >> 3, seg = q & 7;
            cp_async16(&f32s[st * 2048 + (wid * 16 + r) * 32 + seg * 4],
                       src0 + r * HID + seg * 4);
        }
        asm volatile("cp.async.commit_group;");
    };
    auto convert = [&](int ch, int st) {
#pragma unroll
        for (int u = 0; u < 4; u++) {
            int q = lane + u * 32;
            int r = q >> 3, seg = q & 7;
            int rr = wid * 16 + r;
            float4 v = *reinterpret_cast<const float4*>(
                &f32s[st * 2048 + rr * 32 + seg * 4]);
            uint32_t b0, b1;
            asm("cvt.rn.satfinite.bf16x2.f32 %0, %1, %2;" : "=r"(b0) : "f"(v.y), "f"(v.x));
            asm("cvt.rn.satfinite.bf16x2.f32 %0, %1, %2;" : "=r"(b1) : "f"(v.w), "f"(v.z));
            uint2 pk = {b0, b1};
            *reinterpret_cast<uint2*>(tile + rr * ASTRIDE + (ch & 1) * 64 + seg * 8) = pk;
        }
    };

    issue(0, 0); issue(1, 1); issue(2, 2);

    const int rowA = wid * 16 + (lane & 7) + ((lane >> 3) & 1) * 8;
    const int aoff = rowA * ASTRIDE + ((lane >> 4) * 16);

    for (int ch = 0; ch < 24; ch++) {
        if (ch < 22)       asm volatile("cp.async.wait_group 2;");
        else if (ch == 22) asm volatile("cp.async.wait_group 1;");
        else               asm volatile("cp.async.wait_group 0;");
        convert(ch, ch & 3);                   // own rows: no barrier needed
        if (ch + 3 < 24) issue(ch + 3, (ch + 3) & 3);

        const uint32_t abase = smem_u32(tile + aoff) + (ch & 1) * 64;
#pragma unroll
        for (int ksub = 0; ksub < 2; ksub++) {
            uint32_t a0, a1, a2, a3;
            asm volatile("ldmatrix.sync.aligned.m8n8.x4.shared.b16 {%0,%1,%2,%3}, [%4];"
                : "=r"(a0), "=r"(a1), "=r"(a2), "=r"(a3)
                : "r"(abase + ksub * 32));
            const int fbase = ((ch * 2 + ksub) * 3) * 64 + lane * 2;
#pragma unroll
            for (int nt = 0; nt < 3; nt++) {
                uint2 b = *reinterpret_cast<const uint2*>(&g_wfrag[fbase + nt * 64]);
                asm volatile("mma.sync.aligned.m16n8k16.row.col.f32.bf16.bf16.f32 "
                    "{%0,%1,%2,%3}, {%4,%5,%6,%7}, {%8,%9}, {%0,%1,%2,%3};"
                    : "+f"(acc[nt][0]), "+f"(acc[nt][1]), "+f"(acc[nt][2]), "+f"(acc[nt][3])
                    : "r"(a0), "r"(a1), "r"(a2), "r"(a3), "r"(b.x), "r"(b.y));
            }
        }
    }
    __syncthreads();   // all warps done with usm before epilogue reuse

    // epilogue: frag -> emx -> smem -> coalesced store
    {
        float* smf = reinterpret_cast<float*>(usm);
        const int r0 = wid * 16 + (lane >> 2);
#pragma unroll
        for (int nt = 0; nt < 3; nt++) {
            int c = nt * 8 + (lane & 3) * 2;
            if (c < NC) {
                float bc = bias[c];
                smf[r0 * NC + c]       = fast_ex2((acc[nt][0] + bc) * L2E);
                smf[(r0 + 8) * NC + c] = fast_ex2((acc[nt][2] + bc) * L2E);
            }
            if (c + 1 < NC) {
                float bc = bias[c + 1];
                smf[r0 * NC + c + 1]       = fast_ex2((acc[nt][1] + bc) * L2E);
                smf[(r0 + 8) * NC + c + 1] = fast_ex2((acc[nt][3] + bc) * L2E);
            }
        }
        __syncthreads();
        float4* dst = reinterpret_cast<float4*>(g_emx + (uint64_t)row0 * NC);
        const float4* src = reinterpret_cast<const float4*>(smf);
        for (int i = tid; i < (BM * NC) / 4; i += 128) dst[i] = src[i];
    }

    // ================= role assignment =================
    __threadfence();
    if (tid == 0) s_role = atomicAdd(&g_bcnt[batch], 1);
    __syncthreads();
    const int role = s_role;
    if (role == 7 && tid == 0) g_bcnt[batch] = 0;   // all 8 arrived; replay-safe
    if (role < 5) return;

    // ================= labels: dtype + len (roles 5,6,7) =================
    float* red_f = reinterpret_cast<float*>(usm + 22016);
    int*   red_i = reinterpret_cast<int*>(usm + 22656);

    int okd = 1;
    for (int t = tid; t < SEQ; t += 128) {
        int v = labr[2 * t + 1];
        if (v != 0 && v != -1) okd = 0;
    }
    __syncthreads();
    int is64 = __syncthreads_and(okd);
    const int lbase = is64 ? batch * SEQ * 2 : batch * SEQ;
    const int lstep = is64 ? 2 : 1;
#define LAB(t) labr[lbase + (t) * lstep]
    {
        int cnt = 0;
        for (int t = tid; t < SEQ; t += 128)
            if (LAB(t) != -100) cnt++;
        red_i[tid] = cnt;
        __syncthreads();
        for (int s = 64; s > 0; s >>= 1) {
            if (tid < s) red_i[tid] += red_i[tid + s];
            __syncthreads();
        }
        if (tid == 0) s_len = red_i[0];
        __syncthreads();
    }
    const int len = s_len;
    const int mid = (len + 1) >> 1;       // len>=256 so both halves nonempty
    const float* emx_g = g_emx + batch * EM_STRIDE;

    float* emx_s    = reinterpret_cast<float*>(usm);              // <=21504 B
    float (*av)[24] = reinterpret_cast<float(*)[24]>(usm + 21504);

    if (role == 5) {
        // ---------- numerator (log2 domain) ----------
        float pa = 0.f;
        for (int t = tid; t < SEQ; t += 128) {
            int l = LAB(t);
            if (l != -100) {
                if (t == 0) {
                    pa += start_t[l] * L2E + fast_lg2(emx_g[l]);
                } else {
                    int lp = LAB(t - 1);
                    pa += fast_lg2(emx_g[t * NC + l]) + trans[lp * NC + l] * L2E;
                }
            }
        }
        red_f[tid] = pa;
        __syncthreads();
        for (int s = 64; s > 0; s >>= 1) {
            if (tid < s) red_f[tid] += red_f[tid + s];
            __syncthreads();
        }
        if (tid == 0)
            g_num[batch] = red_f[0] + end_t[LAB(len - 1)] * L2E;
    } else if (role == 7) {
        // ---------- forward scan: alpha over [0, mid) ----------
        for (int i = tid; i < mid * NC; i += 128) emx_s[i] = emx_g[i];
        __syncthreads();
        if (tid < 32) {
            const int j = lane < NC ? lane : NC - 1;
            float tl[24];
#pragma unroll
            for (int i = 0; i < NC; i++) tl[i] = fast_ex2(trans[i * NC + j] * L2E);
            tl[21] = tl[22] = tl[23] = 0.f;
            uint64_t tl2[12];
#pragma unroll
            for (int p = 0; p < 12; p++) PACK2(tl2[p], tl[2 * p], tl[2 * p + 1]);

            float a = fast_ex2(start_t[j] * L2E) * emx_s[j];
            if (lane < NC)  av[0][lane] = a;
            if (lane >= NC && lane < 24) { av[0][lane] = 0.f; av[1][lane] = 0.f; }
            int offe = 0, buf = 0;
            for (int t = 1; t < mid; t++) {
                float emn = emx_s[t * NC + j];
                __syncwarp();
                const ulonglong2* vp = reinterpret_cast<const ulonglong2*>(av[buf]);
                ulonglong2 u0 = vp[0], u1 = vp[1], u2 = vp[2];
                ulonglong2 u3 = vp[3], u4 = vp[4], u5 = vp[5];
                uint32_t lo0 = (uint32_t)u0.x;
                int   e     = (int)((lo0 >> 23) & 255) - 127;
                float sclem = __int_as_float((127 - e) << 23) * emn;
                offe += e;
                float s;
                MATVEC2(s, u0, u1, u2, tl2);
                a = s * sclem;
                buf ^= 1;
                if (lane < NC) av[buf][lane] = a;
            }
            __syncwarp();
            if (lane < 24) g_half[batch][0][lane] = (lane < NC) ? a : 0.f;
            if (lane == 0) g_hoffe[batch][0] = (float)offe;
        }
    } else {
        // ---------- backward scan: beta over [mid, len) ----------
        const int nrows = len - mid;
        for (int i = tid; i < nrows * NC; i += 128)
            emx_s[i] = emx_g[mid * NC + i];
        __syncthreads();
        if (tid < 32) {
            const int j = lane < NC ? lane : NC - 1;
            float tb[24];                   // row j of T (linear)
#pragma unroll
            for (int k = 0; k < NC; k++) tb[k] = fast_ex2(trans[j * NC + k] * L2E);
            tb[21] = tb[22] = tb[23] = 0.f;
            uint64_t tb2[12];
#pragma unroll
            for (int p = 0; p < 12; p++) PACK2(tb2[p], tb[2 * p], tb[2 * p + 1]);

            float b = fast_ex2(end_t[j] * L2E);   // beta_{len-1}
            int offe = 0, buf = 0;
            if (lane >= NC && lane < 24) { av[0][lane] = 0.f; av[1][lane] = 0.f; }
            for (int t = len - 1; t >= mid; t--) {
                float d = b * emx_s[(t - mid) * NC + j];
                if (lane < NC) av[buf][lane] = d;
                __syncwarp();
                const ulonglong2* vp = reinterpret_cast<const ulonglong2*>(av[buf]);
                ulonglong2 u0 = vp[0], u1 = vp[1], u2 = vp[2];
                ulonglong2 u3 = vp[3], u4 = vp[4], u5 = vp[5];
                uint32_t lo0 = (uint32_t)u0.x;
                int   e   = (int)((lo0 >> 23) & 255) - 127;
                float scl = __int_as_float((127 - e) << 23);
                offe += e;
                float s;
                MATVEC2(s, u0, u1, u2, tb2);
                b = s * scl;
                buf ^= 1;
            }
            __syncwarp();
            if (lane < 24) g_half[batch][1][lane] = (lane < NC) ? b : 0.f;
            if (lane == 0) g_hoffe[batch][1] = (float)offe;
        }
    }
#undef LAB

    // ================= combine: last of 3 publishers =================
    __syncthreads();
    __threadfence();
    if (tid == 0) s_pub = atomicAdd(&g_scnt[batch], 1);
    __syncthreads();
    if (s_pub != 2) return;
    __threadfence();
    if (tid == 0) g_scnt[batch] = 0;                 // replay-safe

    if (tid < 32) {
        float ex = (lane < NC) ? g_half[batch][0][lane] * g_half[batch][1][lane] : 0.f;
#pragma unroll
        for (int d = 16; d > 0; d >>= 1)
            ex += __shfl_xor_sync(0xffffffffu, ex, d);
        if (lane == 0)
            g_res[batch] = g_hoffe[batch][0] + g_hoffe[batch][1] +
                           fast_lg2(ex) - g_num[batch];
    }

    // ================= final loss: 64th combiner reduces =================
    __syncthreads();
    __threadfence();
    if (tid == 0) s_last = (atomicAdd(&g_done, 1) == BATCH - 1);
    __syncthreads();
    if (s_last && tid < 32) {
        float v = g_res[tid] + g_res[tid + 32];
#pragma unroll
        for (int d = 16; d > 0; d >>= 1)
            v += __shfl_xor_sync(0xffffffffu, v, d);
        if (tid == 0) {
            out[0] = v * (1.0f / (64.0f * L2E));
            g_done = 0;                              // replay-safe
        }
    }
}

// ---------------------------------------------------------------------------
extern "C" void kernel_launch(void* const* d_in, const int* in_sizes, int n_in,
                              void* d_out, int out_size)
{
    const float* hidden = nullptr;
    const float* W      = nullptr;
    const float* trans  = nullptr;
    const int*   labels = nullptr;
    const float* small[3] = {nullptr, nullptr, nullptr};
    int nsmall = 0;

    for (int i = 0; i < n_in; i++) {
        switch (in_sizes[i]) {
            case BATCH * SEQ * HID: hidden = (const float*)d_in[i]; break;
            case HID * NC:          W      = (const float*)d_in[i]; break;
            case NC * NC:           trans  = (const float*)d_in[i]; break;
            case BATCH * SEQ:       labels = (const int*)d_in[i];   break;
            case NC: if (nsmall < 3) small[nsmall++] = (const float*)d_in[i]; break;
            default: break;
        }
    }
    const float* bias    = small[0];
    const float* start_t = small[1];
    const float* end_t   = small[2];

    pack_w_kernel<<<(NFRAG * 64 + 255) / 256, 256>>>(W);
    fused_kernel<<<512, 128>>>(hidden, bias, start_t, end_t, trans, labels,
                               (float*)d_out);
}